// round 10
// baseline (speedup 1.0000x reference)
#include <cuda_runtime.h>
#include <math.h>

#define E_   3072
#define D_   128
#define H_   8
#define HD_  16
#define R_   64
#define FF_  512
#define L_   3
#define CAP_ 128
#define NB_  96      // persistent blocks; 32 rows each; <= SM count -> co-resident

// ---------------- scratch (no allocations allowed) ----------------
#define OFF_H    0
#define OFF_Q    393216          // qkv buffer 0 (intra): q,k,v contiguous
#define OFF_ATT  1572864
#define OFF_MID  2359296
#define OFF_RBF  3932160
#define OFF_PX   4128768
#define OFF_X    4137984
#define OFF_META 4147200
#define OFF_RBFW 4159488
#define OFF_Q2   4945920         // qkv buffer 1 (inter): q,k,v contiguous
#define TOTAL_F  6125568

__device__ __align__(16) float g_buf[TOTAL_F];
__device__ int g_ilist[E_ * CAP_];
__device__ int g_xlist[E_ * CAP_];
__device__ int g_icnt[E_];
__device__ int g_xcnt[E_];
__device__ unsigned g_sync_cnt = 0;   // monotonic grid barrier (replay-safe)

// ---------------- grid-wide barrier (all NB_ blocks co-resident) ----------------
__device__ __forceinline__ void gsync() {
    __threadfence();
    __syncthreads();
    if (threadIdx.x == 0) {
        unsigned arrival = atomicAdd(&g_sync_cnt, 1u);
        unsigned target = (arrival / NB_ + 1u) * NB_;
        while (atomicAdd(&g_sync_cnt, 0u) < target) { __nanosleep(32); }
        __threadfence();
    }
    __syncthreads();
}

// ---------------- packed f32x2 helpers (Blackwell FFMA2) ----------------
typedef unsigned long long ull;
__device__ __forceinline__ ull pack2(float lo, float hi) {
    ull r; asm("mov.b64 %0, {%1, %2};" : "=l"(r) : "f"(lo), "f"(hi)); return r;
}
__device__ __forceinline__ ull dup2(float v) {
    ull r; asm("mov.b64 %0, {%1, %1};" : "=l"(r) : "f"(v)); return r;
}
__device__ __forceinline__ ull fma2(ull a, ull b, ull c) {
    ull d; asm("fma.rn.f32x2 %0, %1, %2, %3;" : "=l"(d) : "l"(a), "l"(b), "l"(c)); return d;
}
__device__ __forceinline__ float2 unpk(ull v) {
    float lo, hi; asm("mov.b64 {%0, %1}, %2;" : "=f"(lo), "=f"(hi) : "l"(v));
    return make_float2(lo, hi);
}

// ---------------- prep: edge meta + rbf + zero px + copy x ----------------
__global__ void prep_kernel(const int* __restrict__ ei, const int* __restrict__ bid,
                            const float* __restrict__ nc, const float* __restrict__ ec,
                            int4* __restrict__ meta, float* __restrict__ rbf,
                            float* __restrict__ px, float* __restrict__ xb) {
    int e = blockIdx.x * 128 + threadIdx.x;
    if (e >= E_) return;
    int s = ei[e], d = ei[E_ + e];
    meta[e] = make_int4(s, d, bid[s], bid[d]);
    px[e*3+0] = 0.f; px[e*3+1] = 0.f; px[e*3+2] = 0.f;
    xb[e*3+0] = ec[e*3+0]; xb[e*3+1] = ec[e*3+1]; xb[e*3+2] = ec[e*3+2];
    float dx = nc[d*3+0] - nc[s*3+0];
    float dy = nc[d*3+1] - nc[s*3+1];
    float dz = nc[d*3+2] - nc[s*3+2];
    float dist = sqrtf(dx*dx + dy*dy + dz*dz);
    float t = fminf(dist * 0.1f, 1.0f);
    float fc = 0.5f * (cosf(3.14159265358979323846f * t) + 1.0f);
    const float inw = 64.0f / 10.0f;   // 1/width, width = CUTOFF/R
    #pragma unroll 8
    for (int r = 0; r < R_; r++) {
        float c = 10.0f * (float)r / 63.0f;   // linspace(0,10,64)
        float u = (dist - c) * inw;
        rbf[e * R_ + r] = expf(-u * u) * fc;
    }
}

// ---------------- build neighbor lists (once; layer/head-invariant) ----------
__global__ void __launch_bounds__(128) build_kernel(const int4* __restrict__ meta) {
    __shared__ int ci, cx;
    int i = blockIdx.x, tid = threadIdx.x;
    if (tid == 0) { ci = 0; cx = 0; }
    __syncthreads();
    int4 mi = meta[i];
    for (int j = tid; j < E_; j += 128) {
        int4 mj = meta[j];
        bool ip = (mi.z == mj.z) && (mi.w == mj.w);
        bool share = (mi.x == mj.x) || (mi.x == mj.y) || (mi.y == mj.x) || (mi.y == mj.y);
        if (ip || (i == j)) {
            int p = atomicAdd(&ci, 1);
            if (p < CAP_) g_ilist[i * CAP_ + p] = j;
        }
        if ((share && !ip) || (i == j)) {
            int p = atomicAdd(&cx, 1);
            if (p < CAP_) g_xlist[i * CAP_ + p] = j;
        }
    }
    __syncthreads();
    if (tid == 0) {
        g_icnt[i] = min(ci, CAP_);
        g_xcnt[i] = min(cx, CAP_);
    }
}

// ============ GEMM tile device fn: 32x128 tile, 256 threads, double-buffered =====
// A [.,K] row-major (lda=K), B [K,Ntot], C row-major ld=Ntot, tile rows m0..m0+31,
// cols cb..cb+127. Warp ty owns rows m0+4ty..+3 across all 128 cols.
// EPI 0: C = A@B
// EPI 5: C = A@B (+res if res!=null)
// EPI 2: C = silu(A@B + bias)
// EPI 3: C = LN(res + A@B)*g + b
// EPI 4: t = LN(res + A@B + bias)*g + b; gate=tanh(t@Wc+bc); x+=gate*(x-px); px=0;
//        C = t (+extra)
template<int EPI>
__device__ void gemm_tile(
    const float* __restrict__ A, const float* __restrict__ B,
    float* C, const float* res, int m0, int cb, int K, int Ntot,
    const float* __restrict__ bias,
    const float* __restrict__ lng, const float* __restrict__ lnb,
    const float* __restrict__ Wc, const float* __restrict__ bc,
    float* px, float* x, const float* __restrict__ extra,
    float* As /* [2][16*34] k-major */, float (*Bs)[16][128])
{
    int tid = threadIdx.x, tx = tid & 31, ty = tid >> 5;
    __syncthreads();                    // smem reuse + same-block global RAW
    int nt = K >> 4;
    int am = tid >> 2, ak = (tid & 3) << 2;          // A loaders: tid<128
    int br0 = tid >> 5, bc4 = (tid & 31) << 2;       // B rows 0..7 / 8..15
    int br1 = br0 + 8;

    float4 pa = make_float4(0.f, 0.f, 0.f, 0.f), pb0, pb1;
    if (tid < 128) pa = *(const float4*)&A[(size_t)(m0 + am) * K + ak];
    pb0 = *(const float4*)&B[(size_t)br0 * Ntot + cb + bc4];
    pb1 = *(const float4*)&B[(size_t)br1 * Ntot + cb + bc4];
    if (tid < 128) {
        As[(ak + 0) * 34 + am] = pa.x;
        As[(ak + 1) * 34 + am] = pa.y;
        As[(ak + 2) * 34 + am] = pa.z;
        As[(ak + 3) * 34 + am] = pa.w;
    }
    *(float4*)&Bs[0][br0][bc4] = pb0;
    *(float4*)&Bs[0][br1][bc4] = pb1;
    __syncthreads();

    ull c2[2][4];
    #pragma unroll
    for (int p = 0; p < 2; p++)
        #pragma unroll
        for (int c = 0; c < 4; c++) c2[p][c] = 0ULL;

    for (int t = 0; t < nt; t++) {
        int cur = t & 1;
        if (t + 1 < nt) {               // register prefetch overlaps compute
            int k0 = (t + 1) << 4;
            if (tid < 128) pa = *(const float4*)&A[(size_t)(m0 + am) * K + k0 + ak];
            pb0 = *(const float4*)&B[(size_t)(k0 + br0) * Ntot + cb + bc4];
            pb1 = *(const float4*)&B[(size_t)(k0 + br1) * Ntot + cb + bc4];
        }
        const float* Ac = As + cur * (16 * 34);
        #pragma unroll
        for (int k = 0; k < 16; k++) {
            float2 a01 = *(const float2*)&Ac[k * 34 + ty * 4];
            float2 a23 = *(const float2*)&Ac[k * 34 + ty * 4 + 2];
            float4 bv  = *(const float4*)&Bs[cur][k][tx << 2];
            ull A01 = pack2(a01.x, a01.y);
            ull A23 = pack2(a23.x, a23.y);
            ull D0 = dup2(bv.x), D1 = dup2(bv.y), D2 = dup2(bv.z), D3 = dup2(bv.w);
            c2[0][0] = fma2(A01, D0, c2[0][0]);  c2[1][0] = fma2(A23, D0, c2[1][0]);
            c2[0][1] = fma2(A01, D1, c2[0][1]);  c2[1][1] = fma2(A23, D1, c2[1][1]);
            c2[0][2] = fma2(A01, D2, c2[0][2]);  c2[1][2] = fma2(A23, D2, c2[1][2]);
            c2[0][3] = fma2(A01, D3, c2[0][3]);  c2[1][3] = fma2(A23, D3, c2[1][3]);
        }
        if (t + 1 < nt) {
            int nb = cur ^ 1;
            float* An = As + nb * (16 * 34);
            if (tid < 128) {
                An[(ak + 0) * 34 + am] = pa.x;
                An[(ak + 1) * 34 + am] = pa.y;
                An[(ak + 2) * 34 + am] = pa.z;
                An[(ak + 3) * 34 + am] = pa.w;
            }
            *(float4*)&Bs[nb][br0][bc4] = pb0;
            *(float4*)&Bs[nb][br1][bc4] = pb1;
        }
        __syncthreads();
    }

    float val[4][4];
    #pragma unroll
    for (int p = 0; p < 2; p++)
        #pragma unroll
        for (int c = 0; c < 4; c++) {
            float2 u = unpk(c2[p][c]);
            val[2*p + 0][c] = u.x;
            val[2*p + 1][c] = u.y;
        }
    int cg = cb + (tx << 2);
    int r0 = m0 + ty * 4;

    if (EPI == 0 || EPI == 5) {
        #pragma unroll
        for (int i = 0; i < 4; i++) {
            float4 o = make_float4(val[i][0], val[i][1], val[i][2], val[i][3]);
            if (EPI == 5 && res) {
                float4 rv = *(const float4*)&res[(size_t)(r0 + i) * Ntot + cg];
                o.x += rv.x; o.y += rv.y; o.z += rv.z; o.w += rv.w;
            }
            *(float4*)&C[(size_t)(r0 + i) * Ntot + cg] = o;
        }
        return;
    }
    if (EPI == 2) {
        float4 bv = *(const float4*)&bias[cg];
        #pragma unroll
        for (int i = 0; i < 4; i++) {
            float v0 = val[i][0] + bv.x, v1 = val[i][1] + bv.y;
            float v2 = val[i][2] + bv.z, v3 = val[i][3] + bv.w;
            v0 = v0 / (1.0f + __expf(-v0));
            v1 = v1 / (1.0f + __expf(-v1));
            v2 = v2 / (1.0f + __expf(-v2));
            v3 = v3 / (1.0f + __expf(-v3));
            *(float4*)&C[(size_t)(r0 + i) * Ntot + cg] = make_float4(v0, v1, v2, v3);
        }
        return;
    }

    // EPI 3 / 4: residual (+bias), row LayerNorm (warp owns full rows)
    float4 bv = make_float4(0.f, 0.f, 0.f, 0.f);
    if (EPI == 4) bv = *(const float4*)&bias[cg];
    #pragma unroll
    for (int i = 0; i < 4; i++) {
        float4 rv = *(const float4*)&res[(size_t)(r0 + i) * 128 + cg];
        val[i][0] += rv.x + bv.x;  val[i][1] += rv.y + bv.y;
        val[i][2] += rv.z + bv.z;  val[i][3] += rv.w + bv.w;
    }
    float s[4], sq[4];
    #pragma unroll
    for (int i = 0; i < 4; i++) {
        s[i]  = val[i][0] + val[i][1] + val[i][2] + val[i][3];
        sq[i] = val[i][0]*val[i][0] + val[i][1]*val[i][1]
              + val[i][2]*val[i][2] + val[i][3]*val[i][3];
    }
    #pragma unroll
    for (int o = 16; o > 0; o >>= 1) {
        #pragma unroll
        for (int i = 0; i < 4; i++) {
            s[i]  += __shfl_xor_sync(0xffffffffu, s[i],  o);
            sq[i] += __shfl_xor_sync(0xffffffffu, sq[i], o);
        }
    }
    float4 g4 = *(const float4*)&lng[cg];
    float4 b4 = *(const float4*)&lnb[cg];
    float gd[4];
    float4 wc4 = make_float4(0.f, 0.f, 0.f, 0.f);
    if (EPI == 4) wc4 = *(const float4*)&Wc[cg];
    #pragma unroll
    for (int i = 0; i < 4; i++) {
        float mean = s[i] * (1.0f / 128.0f);
        float var  = fmaxf(sq[i] * (1.0f / 128.0f) - mean * mean, 0.0f);
        float rstd = rsqrtf(var + 1e-5f);
        float h0 = (val[i][0] - mean) * rstd * g4.x + b4.x;
        float h1 = (val[i][1] - mean) * rstd * g4.y + b4.y;
        float h2 = (val[i][2] - mean) * rstd * g4.z + b4.z;
        float h3 = (val[i][3] - mean) * rstd * g4.w + b4.w;
        if (EPI == 4) {
            gd[i] = h0*wc4.x + h1*wc4.y + h2*wc4.z + h3*wc4.w;   // gate uses LN output
            if (extra) {                                          // + next layer's rbfW
                float4 ev = *(const float4*)&extra[(size_t)(r0 + i) * 128 + cg];
                h0 += ev.x; h1 += ev.y; h2 += ev.z; h3 += ev.w;
            }
        }
        *(float4*)&C[(size_t)(r0 + i) * 128 + cg] = make_float4(h0, h1, h2, h3);
    }
    if (EPI == 4) {
        #pragma unroll
        for (int o = 16; o > 0; o >>= 1)
            #pragma unroll
            for (int i = 0; i < 4; i++)
                gd[i] += __shfl_xor_sync(0xffffffffu, gd[i], o);
        if (tx < 3) {
            float bcv = bc[0];
            #pragma unroll
            for (int i = 0; i < 4; i++) {
                int r = r0 + i;
                float gt = tanhf(gd[i] + bcv);
                float xv = x[r * 3 + tx];
                float pv = px[r * 3 + tx];
                x[r * 3 + tx]  = xv + gt * (xv - pv);
                px[r * 3 + tx] = 0.0f;
            }
        }
    }
}

// -------- attention stage: block handles its own 32 rows x 8 heads = 256 tasks ----
// Warp processes 2 tasks concurrently (independent chains -> ILP hides L2 latency).
// Lane split per task: d = lane&15 head-dim, half = lane>>4 splits neighbor list;
// in-loop shuffles use per-half masks (trip counts differ when n odd).
template<bool INTRA>
__device__ void attn_stage(const float* __restrict__ q, const float* __restrict__ k,
                           const float* __restrict__ v, const float* __restrict__ x,
                           float* out, float* px, int blk)
{
    int warp = threadIdx.x >> 5, lane = threadIdx.x & 31;
    int d = lane & 15, half = lane >> 4;
    unsigned hm = half ? 0xffff0000u : 0x0000ffffu;
    int base = blk * 32;

    for (int it = 0; it < 16; it++) {
        int tA = warp + 8 * it;          // tasks 0..127
        int tB = tA + 128;               // tasks 128..255
        int iA = base + (tA >> 3), oA = (tA & 7) * HD_;
        int iB = base + (tB >> 3), oB = (tB & 7) * HD_;
        float qA = q[iA * D_ + oA + d];
        float qB = q[iB * D_ + oB + d];
        int nA = INTRA ? g_icnt[iA] : g_xcnt[iA];
        int nB = INTRA ? g_icnt[iB] : g_xcnt[iB];
        const int* lA = (INTRA ? g_ilist : g_xlist) + iA * CAP_;
        const int* lB = (INTRA ? g_ilist : g_xlist) + iB * CAP_;

        float mA = -1e30f, sA = 0.f, aA = 0.f, axA = 0.f;
        float mB = -1e30f, sB = 0.f, aB = 0.f, axB = 0.f;
        int steps = max(nA, nB);

        for (int t = half; t < steps; t += 2) {
            if (t < nA) {                                  // uniform within the half
                int j = lA[t];
                float s = qA * k[j * D_ + oA + d];
                s += __shfl_xor_sync(hm, s, 8);
                s += __shfl_xor_sync(hm, s, 4);
                s += __shfl_xor_sync(hm, s, 2);
                s += __shfl_xor_sync(hm, s, 1);
                s *= 0.25f;
                float vd = v[j * D_ + oA + d];
                float mn = fmaxf(mA, s);
                float cc = __expf(mA - mn), p = __expf(s - mn);
                sA = sA * cc + p;
                aA = aA * cc + p * vd;
                if (INTRA && d < 3) axA = axA * cc + p * x[j * 3 + d];
                mA = mn;
            }
            if (t < nB) {
                int j = lB[t];
                float s = qB * k[j * D_ + oB + d];
                s += __shfl_xor_sync(hm, s, 8);
                s += __shfl_xor_sync(hm, s, 4);
                s += __shfl_xor_sync(hm, s, 2);
                s += __shfl_xor_sync(hm, s, 1);
                s *= 0.25f;
                float vd = v[j * D_ + oB + d];
                float mn = fmaxf(mB, s);
                float cc = __expf(mB - mn), p = __expf(s - mn);
                sB = sB * cc + p;
                aB = aB * cc + p * vd;
                if (INTRA && d < 3) axB = axB * cc + p * x[j * 3 + d];
                mB = mn;
            }
        }

        // merge the two halves of each task (all lanes re-converged -> full mask)
        {
            float m2 = __shfl_xor_sync(0xffffffffu, mA, 16);
            float l2 = __shfl_xor_sync(0xffffffffu, sA, 16);
            float a2 = __shfl_xor_sync(0xffffffffu, aA, 16);
            float mn = fmaxf(mA, m2);
            float c1 = __expf(mA - mn), c2x = __expf(m2 - mn);
            sA = sA * c1 + l2 * c2x;
            aA = aA * c1 + a2 * c2x;
            if (INTRA) {
                float x2 = __shfl_xor_sync(0xffffffffu, axA, 16);
                axA = axA * c1 + x2 * c2x;
            }
            float inv = 1.0f / sA;
            if (half == 0) {
                out[iA * D_ + oA + d] = aA * inv;
                if (INTRA && d < 3) atomicAdd(&px[iA * 3 + d], axA * inv * 0.125f);
            }
        }
        {
            float m2 = __shfl_xor_sync(0xffffffffu, mB, 16);
            float l2 = __shfl_xor_sync(0xffffffffu, sB, 16);
            float a2 = __shfl_xor_sync(0xffffffffu, aB, 16);
            float mn = fmaxf(mB, m2);
            float c1 = __expf(mB - mn), c2x = __expf(m2 - mn);
            sB = sB * c1 + l2 * c2x;
            aB = aB * c1 + a2 * c2x;
            if (INTRA) {
                float x2 = __shfl_xor_sync(0xffffffffu, axB, 16);
                axB = axB * c1 + x2 * c2x;
            }
            float inv = 1.0f / sB;
            if (half == 0) {
                out[iB * D_ + oB + d] = aB * inv;
                if (INTRA && d < 3) atomicAdd(&px[iB * 3 + d], axB * inv * 0.125f);
            }
        }
    }
}

// ---------------- the persistent megakernel: whole 3-layer pipeline -------------
// QKV double buffering: intra attention always uses qkv buffer 0, inter uses
// buffer 1. This removes the WAR hazard (R8's bug): the gsync before attention
// stage s guarantees all blocks finished attention stage s-1, and buffer b is
// only rewritten two stages after its last read -> always protected by a gsync.
__global__ void __launch_bounds__(256) mega_kernel(
    const float* __restrict__ edge_features,
    const float* __restrict__ Wq_a, const float* __restrict__ Wk_a,
    const float* __restrict__ Wv_a, const float* __restrict__ Wo_a,
    const float* __restrict__ Wq_e, const float* __restrict__ Wk_e,
    const float* __restrict__ Wv_e, const float* __restrict__ Wo_e,
    const float* __restrict__ W1, const float* __restrict__ b1,
    const float* __restrict__ W2, const float* __restrict__ b2,
    const float* __restrict__ ln1g, const float* __restrict__ ln1b,
    const float* __restrict__ ln2g, const float* __restrict__ ln2b,
    const float* __restrict__ ln3g, const float* __restrict__ ln3b,
    const float* __restrict__ Wrbf, const float* __restrict__ Wc,
    const float* __restrict__ bc,
    float* h, float* qkv0, float* qkv1, float* att, float* mid,
    float* rbf, float* rbfW, float* px, float* xb)
{
    __shared__ __align__(16) float As[2 * 16 * 34];
    __shared__ __align__(16) float Bs[2][16][128];
    int blk = blockIdx.x;
    int m0 = blk * 32;

    // stage 0: rbfW_l = rbf @ Wrbf[l]; l=0 lands in h (+edge_features)
    gemm_tile<5>(rbf, Wrbf,            h,            edge_features, m0, 0, R_, 128,
                 nullptr, nullptr, nullptr, nullptr, nullptr, nullptr, nullptr, nullptr, As, Bs);
    gemm_tile<5>(rbf, Wrbf + R_*D_,    rbfW,         nullptr,       m0, 0, R_, 128,
                 nullptr, nullptr, nullptr, nullptr, nullptr, nullptr, nullptr, nullptr, As, Bs);
    gemm_tile<5>(rbf, Wrbf + 2*R_*D_,  rbfW + E_*D_, nullptr,       m0, 0, R_, 128,
                 nullptr, nullptr, nullptr, nullptr, nullptr, nullptr, nullptr, nullptr, As, Bs);

    for (int l = 0; l < L_; l++) {
        const int DD = D_ * D_;
        const float* extra = (l < 2) ? (rbfW + (size_t)l * E_ * D_) : nullptr;

        // --- intra attention block (qkv buffer 0) ---
        {
            const float* W[3] = { Wq_a + l*DD, Wk_a + l*DD, Wv_a + l*DD };
            for (int z = 0; z < 3; z++)
                gemm_tile<0>(h, W[z], qkv0 + (size_t)z * E_ * D_, nullptr, m0, 0, D_, 128,
                             nullptr, nullptr, nullptr, nullptr, nullptr,
                             nullptr, nullptr, nullptr, As, Bs);
        }
        gsync();   // attn reads K/V/x of ALL rows
        attn_stage<true>(qkv0, qkv0 + E_*D_, qkv0 + 2*E_*D_, xb, att, px, blk);
        gemm_tile<3>(att, Wo_a + l*DD, h, h, m0, 0, D_, 128,
                     nullptr, ln1g + l*D_, ln1b + l*D_,
                     nullptr, nullptr, nullptr, nullptr, nullptr, As, Bs);

        // --- inter attention block (qkv buffer 1) ---
        {
            const float* W[3] = { Wq_e + l*DD, Wk_e + l*DD, Wv_e + l*DD };
            for (int z = 0; z < 3; z++)
                gemm_tile<0>(h, W[z], qkv1 + (size_t)z * E_ * D_, nullptr, m0, 0, D_, 128,
                             nullptr, nullptr, nullptr, nullptr, nullptr,
                             nullptr, nullptr, nullptr, As, Bs);
        }
        gsync();
        attn_stage<false>(qkv1, qkv1 + E_*D_, qkv1 + 2*E_*D_, xb, att, nullptr, blk);
        gemm_tile<3>(att, Wo_e + l*DD, h, h, m0, 0, D_, 128,
                     nullptr, ln2g + l*D_, ln2b + l*D_,
                     nullptr, nullptr, nullptr, nullptr, nullptr, As, Bs);

        // --- FFN (all row-local; no grid sync needed) ---
        for (int nb = 0; nb < 4; nb++)
            gemm_tile<2>(h, W1 + (size_t)l * D_ * FF_, mid, nullptr, m0, nb * 128, D_, FF_,
                         b1 + l*FF_, nullptr, nullptr, nullptr, nullptr,
                         nullptr, nullptr, nullptr, As, Bs);
        gemm_tile<4>(mid, W2 + (size_t)l * FF_ * D_, h, h, m0, 0, FF_, 128,
                     b2 + l*D_, ln3g + l*D_, ln3b + l*D_,
                     Wc + l*D_, bc + l, px, xb, extra, As, Bs);
    }
}

// ---------------- output: concat(h, x) ----------------
__global__ void out_kernel(const float* __restrict__ h, const float* __restrict__ x,
                           float* __restrict__ out, int out_size)
{
    int i = blockIdx.x * 256 + threadIdx.x;
    if (i >= out_size) return;
    if (i < E_ * D_)               out[i] = h[i];
    else if (i < E_ * D_ + E_ * 3) out[i] = x[i - E_ * D_];
    else                           out[i] = 0.0f;
}

// ---------------- host ----------------
extern "C" void kernel_launch(void* const* d_in, const int* in_sizes, int n_in,
                              void* d_out, int out_size)
{
    const float* edge_features = (const float*)d_in[0];
    const float* edge_coords   = (const float*)d_in[1];
    const int*   edge_index    = (const int*)  d_in[2];
    const float* node_coords   = (const float*)d_in[3];
    const int*   block_ids     = (const int*)  d_in[4];
    const float* Wq_a = (const float*)d_in[5];
    const float* Wk_a = (const float*)d_in[6];
    const float* Wv_a = (const float*)d_in[7];
    const float* Wo_a = (const float*)d_in[8];
    const float* Wq_e = (const float*)d_in[9];
    const float* Wk_e = (const float*)d_in[10];
    const float* Wv_e = (const float*)d_in[11];
    const float* Wo_e = (const float*)d_in[12];
    const float* W1   = (const float*)d_in[13];
    const float* b1   = (const float*)d_in[14];
    const float* W2   = (const float*)d_in[15];
    const float* b2   = (const float*)d_in[16];
    const float* ln1g = (const float*)d_in[17];
    const float* ln1b = (const float*)d_in[18];
    const float* ln2g = (const float*)d_in[19];
    const float* ln2b = (const float*)d_in[20];
    const float* ln3g = (const float*)d_in[21];
    const float* ln3b = (const float*)d_in[22];
    const float* Wrbf = (const float*)d_in[23];
    const float* Wc   = (const float*)d_in[24];
    const float* bc   = (const float*)d_in[25];

    float* buf = nullptr;
    cudaGetSymbolAddress((void**)&buf, g_buf);
    float* h    = buf + OFF_H;
    float* qkv0 = buf + OFF_Q;
    float* qkv1 = buf + OFF_Q2;
    float* att  = buf + OFF_ATT;
    float* mid  = buf + OFF_MID;
    float* rbf  = buf + OFF_RBF;
    float* px   = buf + OFF_PX;
    float* xb   = buf + OFF_X;
    int4*  meta = (int4*)(buf + OFF_META);
    float* rbfW = buf + OFF_RBFW;

    prep_kernel<<<(E_ + 127) / 128, 128>>>(edge_index, block_ids, node_coords,
                                           edge_coords, meta, rbf, px, xb);
    build_kernel<<<E_, 128>>>(meta);
    mega_kernel<<<NB_, 256>>>(edge_features,
                              Wq_a, Wk_a, Wv_a, Wo_a, Wq_e, Wk_e, Wv_e, Wo_e,
                              W1, b1, W2, b2,
                              ln1g, ln1b, ln2g, ln2b, ln3g, ln3b,
                              Wrbf, Wc, bc,
                              h, qkv0, qkv1, att, mid, rbf, rbfW, px, xb);
    out_kernel<<<(out_size + 255) / 256, 256>>>(h, xb, (float*)d_out, out_size);
}

// round 11
// speedup vs baseline: 2.8586x; 2.8586x over previous
#include <cuda_runtime.h>
#include <math.h>

#define E_   3072
#define D_   128
#define H_   8
#define HD_  16
#define R_   64
#define FF_  512
#define L_   3
#define CAP_ 128

// ---------------- scratch (no allocations allowed) ----------------
#define OFF_H    0
#define OFF_Q    393216          // q,k,v contiguous -> batched GEMM dst
#define OFF_ATT  1572864
#define OFF_MID  2359296
#define OFF_RBF  3932160
#define OFF_PX   4128768
#define OFF_X    4137984
#define OFF_META 4147200
#define OFF_RBFW 4159488
#define TOTAL_F  4945920

__device__ __align__(16) float g_buf[TOTAL_F];
__device__ int g_ilist[E_ * CAP_];
__device__ int g_xlist[E_ * CAP_];
__device__ int g_icnt[E_];
__device__ int g_xcnt[E_];

// ---------------- packed f32x2 helpers (Blackwell FFMA2) ----------------
typedef unsigned long long ull;
__device__ __forceinline__ ull pack2(float lo, float hi) {
    ull r; asm("mov.b64 %0, {%1, %2};" : "=l"(r) : "f"(lo), "f"(hi)); return r;
}
__device__ __forceinline__ ull dup2(float v) {
    ull r; asm("mov.b64 %0, {%1, %1};" : "=l"(r) : "f"(v)); return r;
}
__device__ __forceinline__ ull fma2(ull a, ull b, ull c) {
    ull d; asm("fma.rn.f32x2 %0, %1, %2, %3;" : "=l"(d) : "l"(a), "l"(b), "l"(c)); return d;
}
__device__ __forceinline__ float2 unpk(ull v) {
    float lo, hi; asm("mov.b64 {%0, %1}, %2;" : "=f"(lo), "=f"(hi) : "l"(v));
    return make_float2(lo, hi);
}

// ---------------- prep: edge meta + rbf + zero px + copy x ----------------
__global__ void prep_kernel(const int* __restrict__ ei, const int* __restrict__ bid,
                            const float* __restrict__ nc, const float* __restrict__ ec,
                            int4* __restrict__ meta, float* __restrict__ rbf,
                            float* __restrict__ px, float* __restrict__ xb) {
    int e = blockIdx.x * 128 + threadIdx.x;
    if (e >= E_) return;
    int s = ei[e], d = ei[E_ + e];
    meta[e] = make_int4(s, d, bid[s], bid[d]);
    px[e*3+0] = 0.f; px[e*3+1] = 0.f; px[e*3+2] = 0.f;
    xb[e*3+0] = ec[e*3+0]; xb[e*3+1] = ec[e*3+1]; xb[e*3+2] = ec[e*3+2];
    float dx = nc[d*3+0] - nc[s*3+0];
    float dy = nc[d*3+1] - nc[s*3+1];
    float dz = nc[d*3+2] - nc[s*3+2];
    float dist = sqrtf(dx*dx + dy*dy + dz*dz);
    float t = fminf(dist * 0.1f, 1.0f);
    float fc = 0.5f * (cosf(3.14159265358979323846f * t) + 1.0f);
    const float inw = 64.0f / 10.0f;   // 1/width, width = CUTOFF/R
    #pragma unroll 8
    for (int r = 0; r < R_; r++) {
        float c = 10.0f * (float)r / 63.0f;   // linspace(0,10,64)
        float u = (dist - c) * inw;
        rbf[e * R_ + r] = expf(-u * u) * fc;
    }
}

// ---------------- build neighbor lists (once; layer/head-invariant) ----------
__global__ void __launch_bounds__(128) build_kernel(const int4* __restrict__ meta) {
    __shared__ int ci, cx;
    int i = blockIdx.x, tid = threadIdx.x;
    if (tid == 0) { ci = 0; cx = 0; }
    __syncthreads();
    int4 mi = meta[i];
    for (int j = tid; j < E_; j += 128) {
        int4 mj = meta[j];
        bool ip = (mi.z == mj.z) && (mi.w == mj.w);
        bool share = (mi.x == mj.x) || (mi.x == mj.y) || (mi.y == mj.x) || (mi.y == mj.y);
        if (ip || (i == j)) {
            int p = atomicAdd(&ci, 1);
            if (p < CAP_) g_ilist[i * CAP_ + p] = j;
        }
        if ((share && !ip) || (i == j)) {
            int p = atomicAdd(&cx, 1);
            if (p < CAP_) g_xlist[i * CAP_ + p] = j;
        }
    }
    __syncthreads();
    if (tid == 0) {
        g_icnt[i] = min(ci, CAP_);
        g_xcnt[i] = min(cx, CAP_);
    }
}

// ====== fused GEMM, tile 32x128, 256 threads, double-buffered, f32x2 FMA ======
// A [.,K] rm, B [K,Ntot], C rm ld=Ntot. Warp ty owns rows m0+4ty..+3 (full rows).
// EPI 0: C = A@B; blockIdx.z selects B0/B1/B2, C = C0 + z*M*128        (QKV)
// EPI 5: z selects B; C = A@B (+res if z==0); z=0 -> C0, z>0 -> C12+(z-1)*M*128
// EPI 2: C = silu(A@B + bias)                                          (FFN up)
// EPI 3: C = LN(res + A@B)*g + b                                       (attn o-proj)
// EPI 4: t = LN(res + A@B + bias)*g + b; gate=tanh(t@Wc+bc);
//        x += gate*(x-px); px=0; C = t (+extra = next layer's rbfW)    (FFN down)
template<int EPI>
__global__ void __launch_bounds__(256) gemm_kernel(
    const float* __restrict__ A, const float* __restrict__ B0,
    const float* __restrict__ B1, const float* __restrict__ B2,
    float* C0, float* C12, const float* res, int M, int K, int Ntot,
    const float* __restrict__ bias,
    const float* __restrict__ lng, const float* __restrict__ lnb,
    const float* __restrict__ Wc, const float* __restrict__ bc,
    float* px, float* x, const float* __restrict__ extra)
{
    __shared__ __align__(16) float As[2][16 * 34];   // k-major, stride 34
    __shared__ __align__(16) float Bs[2][16][128];
    int z = blockIdx.z;
    const float* B = (z == 0) ? B0 : ((z == 1) ? B1 : B2);
    float* C;
    if (EPI == 0)      C = C0 + (size_t)z * M * 128;
    else if (EPI == 5) C = (z == 0) ? C0 : (C12 + (size_t)(z - 1) * M * 128);
    else               C = C0;

    int tid = threadIdx.x, tx = tid & 31, ty = tid >> 5;
    int m0 = blockIdx.y << 5, cb = blockIdx.x << 7;
    int nt = K >> 4;
    int am = tid >> 2, ak = (tid & 3) << 2;          // A loaders: tid<128
    int br0 = tid >> 5, bc4 = (tid & 31) << 2;       // B rows 0..7 / 8..15
    int br1 = br0 + 8;

    // prologue: tile 0 -> smem[0]
    float4 pa = make_float4(0.f, 0.f, 0.f, 0.f), pb0, pb1;
    if (tid < 128) pa = *(const float4*)&A[(size_t)(m0 + am) * K + ak];
    pb0 = *(const float4*)&B[(size_t)br0 * Ntot + cb + bc4];
    pb1 = *(const float4*)&B[(size_t)br1 * Ntot + cb + bc4];
    if (tid < 128) {
        As[0][(ak + 0) * 34 + am] = pa.x;
        As[0][(ak + 1) * 34 + am] = pa.y;
        As[0][(ak + 2) * 34 + am] = pa.z;
        As[0][(ak + 3) * 34 + am] = pa.w;
    }
    *(float4*)&Bs[0][br0][bc4] = pb0;
    *(float4*)&Bs[0][br1][bc4] = pb1;
    __syncthreads();

    ull c2[2][4];
    #pragma unroll
    for (int p = 0; p < 2; p++)
        #pragma unroll
        for (int c = 0; c < 4; c++) c2[p][c] = 0ULL;

    for (int t = 0; t < nt; t++) {
        int cur = t & 1;
        if (t + 1 < nt) {               // register prefetch overlaps compute
            int k0 = (t + 1) << 4;
            if (tid < 128) pa = *(const float4*)&A[(size_t)(m0 + am) * K + k0 + ak];
            pb0 = *(const float4*)&B[(size_t)(k0 + br0) * Ntot + cb + bc4];
            pb1 = *(const float4*)&B[(size_t)(k0 + br1) * Ntot + cb + bc4];
        }
        const float* Ac = As[cur];
        #pragma unroll
        for (int k = 0; k < 16; k++) {
            float2 a01 = *(const float2*)&Ac[k * 34 + ty * 4];
            float2 a23 = *(const float2*)&Ac[k * 34 + ty * 4 + 2];
            float4 bv  = *(const float4*)&Bs[cur][k][tx << 2];
            ull A01 = pack2(a01.x, a01.y);
            ull A23 = pack2(a23.x, a23.y);
            ull D0 = dup2(bv.x), D1 = dup2(bv.y), D2 = dup2(bv.z), D3 = dup2(bv.w);
            c2[0][0] = fma2(A01, D0, c2[0][0]);  c2[1][0] = fma2(A23, D0, c2[1][0]);
            c2[0][1] = fma2(A01, D1, c2[0][1]);  c2[1][1] = fma2(A23, D1, c2[1][1]);
            c2[0][2] = fma2(A01, D2, c2[0][2]);  c2[1][2] = fma2(A23, D2, c2[1][2]);
            c2[0][3] = fma2(A01, D3, c2[0][3]);  c2[1][3] = fma2(A23, D3, c2[1][3]);
        }
        if (t + 1 < nt) {
            int nb = cur ^ 1;
            float* An = As[nb];
            if (tid < 128) {
                An[(ak + 0) * 34 + am] = pa.x;
                An[(ak + 1) * 34 + am] = pa.y;
                An[(ak + 2) * 34 + am] = pa.z;
                An[(ak + 3) * 34 + am] = pa.w;
            }
            *(float4*)&Bs[nb][br0][bc4] = pb0;
            *(float4*)&Bs[nb][br1][bc4] = pb1;
        }
        __syncthreads();
    }

    float val[4][4];
    #pragma unroll
    for (int p = 0; p < 2; p++)
        #pragma unroll
        for (int c = 0; c < 4; c++) {
            float2 u = unpk(c2[p][c]);
            val[2*p + 0][c] = u.x;
            val[2*p + 1][c] = u.y;
        }
    int cg = cb + (tx << 2);
    int r0 = m0 + ty * 4;

    if (EPI == 0 || EPI == 5) {
        #pragma unroll
        for (int i = 0; i < 4; i++) {
            float4 o = make_float4(val[i][0], val[i][1], val[i][2], val[i][3]);
            if (EPI == 5 && z == 0) {
                float4 rv = *(const float4*)&res[(size_t)(r0 + i) * Ntot + cg];
                o.x += rv.x; o.y += rv.y; o.z += rv.z; o.w += rv.w;
            }
            *(float4*)&C[(size_t)(r0 + i) * Ntot + cg] = o;
        }
        return;
    }
    if (EPI == 2) {
        float4 bv = *(const float4*)&bias[cg];
        #pragma unroll
        for (int i = 0; i < 4; i++) {
            float v0 = val[i][0] + bv.x, v1 = val[i][1] + bv.y;
            float v2 = val[i][2] + bv.z, v3 = val[i][3] + bv.w;
            v0 = v0 / (1.0f + __expf(-v0));
            v1 = v1 / (1.0f + __expf(-v1));
            v2 = v2 / (1.0f + __expf(-v2));
            v3 = v3 / (1.0f + __expf(-v3));
            *(float4*)&C[(size_t)(r0 + i) * Ntot + cg] = make_float4(v0, v1, v2, v3);
        }
        return;
    }

    // EPI 3 / 4: residual (+bias), row LayerNorm (warp owns full rows)
    float4 bv = make_float4(0.f, 0.f, 0.f, 0.f);
    if (EPI == 4) bv = *(const float4*)&bias[cg];
    #pragma unroll
    for (int i = 0; i < 4; i++) {
        float4 rv = *(const float4*)&res[(size_t)(r0 + i) * 128 + cg];
        val[i][0] += rv.x + bv.x;  val[i][1] += rv.y + bv.y;
        val[i][2] += rv.z + bv.z;  val[i][3] += rv.w + bv.w;
    }
    float s[4], sq[4];
    #pragma unroll
    for (int i = 0; i < 4; i++) {
        s[i]  = val[i][0] + val[i][1] + val[i][2] + val[i][3];
        sq[i] = val[i][0]*val[i][0] + val[i][1]*val[i][1]
              + val[i][2]*val[i][2] + val[i][3]*val[i][3];
    }
    #pragma unroll
    for (int o = 16; o > 0; o >>= 1) {
        #pragma unroll
        for (int i = 0; i < 4; i++) {
            s[i]  += __shfl_xor_sync(0xffffffffu, s[i],  o);
            sq[i] += __shfl_xor_sync(0xffffffffu, sq[i], o);
        }
    }
    float4 g4 = *(const float4*)&lng[cg];
    float4 b4 = *(const float4*)&lnb[cg];
    float gd[4];
    float4 wc4 = make_float4(0.f, 0.f, 0.f, 0.f);
    if (EPI == 4) wc4 = *(const float4*)&Wc[cg];
    #pragma unroll
    for (int i = 0; i < 4; i++) {
        float mean = s[i] * (1.0f / 128.0f);
        float var  = fmaxf(sq[i] * (1.0f / 128.0f) - mean * mean, 0.0f);
        float rstd = rsqrtf(var + 1e-5f);
        float h0 = (val[i][0] - mean) * rstd * g4.x + b4.x;
        float h1 = (val[i][1] - mean) * rstd * g4.y + b4.y;
        float h2 = (val[i][2] - mean) * rstd * g4.z + b4.z;
        float h3 = (val[i][3] - mean) * rstd * g4.w + b4.w;
        if (EPI == 4) {
            gd[i] = h0*wc4.x + h1*wc4.y + h2*wc4.z + h3*wc4.w;   // gate uses LN output
            if (extra) {                                          // + next layer's rbfW
                float4 ev = *(const float4*)&extra[(size_t)(r0 + i) * 128 + cg];
                h0 += ev.x; h1 += ev.y; h2 += ev.z; h3 += ev.w;
            }
        }
        *(float4*)&C[(size_t)(r0 + i) * 128 + cg] = make_float4(h0, h1, h2, h3);
    }
    if (EPI == 4) {
        #pragma unroll
        for (int o = 16; o > 0; o >>= 1)
            #pragma unroll
            for (int i = 0; i < 4; i++)
                gd[i] += __shfl_xor_sync(0xffffffffu, gd[i], o);
        if (tx < 3) {
            float bcv = bc[0];
            #pragma unroll
            for (int i = 0; i < 4; i++) {
                int r = r0 + i;
                float gt = tanhf(gd[i] + bcv);
                float xv = x[r * 3 + tx];
                float pv = px[r * 3 + tx];
                x[r * 3 + tx]  = xv + gt * (xv - pv);
                px[r * 3 + tx] = 0.0f;   // ready for next layer / next replay
            }
        }
    }
}

// ---------------- sparse masked attention: one warp per (query, head) -----------
// Lanes split as (half, d): d = lane&15 is the head-dim, half = lane>>4 splits the
// neighbor list. Streaming softmax; halves merged via shfl at the end.
// In-loop shuffles use per-half masks (halves have different trip counts when n odd).
// INTRA also accumulates px[i] = mean_h sum_j p[h,i,j] * x[j] (atomicAdd, 3 lanes).
template<bool INTRA>
__global__ void __launch_bounds__(256) attn_kernel(
    const float* __restrict__ q, const float* __restrict__ k, const float* __restrict__ v,
    const float* __restrict__ x, float* __restrict__ out, float* __restrict__ px)
{
    int warp = threadIdx.x >> 5, lane = threadIdx.x & 31;
    int i = blockIdx.x * 8 + warp;
    int head = blockIdx.y;
    int off = head * HD_;
    int d = lane & 15, half = lane >> 4;
    unsigned hm = half ? 0xffff0000u : 0x0000ffffu;   // lanes of MY half only

    float qd = q[i * D_ + off + d];
    int n = INTRA ? g_icnt[i] : g_xcnt[i];
    const int* li = (INTRA ? g_ilist : g_xlist) + i * CAP_;

    float m = -1e30f, l = 0.0f, acc = 0.0f, ax = 0.0f;

    for (int t = half; t < n; t += 2) {
        int j = li[t];
        float s = qd * k[j * D_ + off + d];
        s += __shfl_xor_sync(hm, s, 8);
        s += __shfl_xor_sync(hm, s, 4);
        s += __shfl_xor_sync(hm, s, 2);
        s += __shfl_xor_sync(hm, s, 1);
        s *= 0.25f;  // 1/sqrt(16)
        float vd = v[j * D_ + off + d];
        float mn = fmaxf(m, s);
        float cc = __expf(m - mn), p = __expf(s - mn);
        l = l * cc + p;
        acc = acc * cc + p * vd;
        if (INTRA && d < 3) ax = ax * cc + p * x[j * 3 + d];
        m = mn;
    }

    // merge the two halves (all 32 lanes re-converged -> full mask legal)
    float m2 = __shfl_xor_sync(0xffffffffu, m, 16);
    float l2 = __shfl_xor_sync(0xffffffffu, l, 16);
    float a2 = __shfl_xor_sync(0xffffffffu, acc, 16);
    float mn = fmaxf(m, m2);
    float c1 = __expf(m - mn), c2 = __expf(m2 - mn);
    l = l * c1 + l2 * c2;
    acc = acc * c1 + a2 * c2;
    if (INTRA) {
        float x2 = __shfl_xor_sync(0xffffffffu, ax, 16);
        ax = ax * c1 + x2 * c2;
    }
    float inv = 1.0f / l;  // diag always present -> l > 0
    if (half == 0) {
        out[i * D_ + off + d] = acc * inv;
        if (INTRA && d < 3) atomicAdd(&px[i * 3 + d], ax * inv * 0.125f);
    }
}

// ---------------- output: concat(h, x) ----------------
__global__ void out_kernel(const float* __restrict__ h, const float* __restrict__ x,
                           float* __restrict__ out, int out_size)
{
    int i = blockIdx.x * 256 + threadIdx.x;
    if (i >= out_size) return;
    if (i < E_ * D_)               out[i] = h[i];
    else if (i < E_ * D_ + E_ * 3) out[i] = x[i - E_ * D_];
    else                           out[i] = 0.0f;
}

// ---------------- host ----------------
extern "C" void kernel_launch(void* const* d_in, const int* in_sizes, int n_in,
                              void* d_out, int out_size)
{
    const float* edge_features = (const float*)d_in[0];
    const float* edge_coords   = (const float*)d_in[1];
    const int*   edge_index    = (const int*)  d_in[2];
    const float* node_coords   = (const float*)d_in[3];
    const int*   block_ids     = (const int*)  d_in[4];
    const float* Wq_a = (const float*)d_in[5];
    const float* Wk_a = (const float*)d_in[6];
    const float* Wv_a = (const float*)d_in[7];
    const float* Wo_a = (const float*)d_in[8];
    const float* Wq_e = (const float*)d_in[9];
    const float* Wk_e = (const float*)d_in[10];
    const float* Wv_e = (const float*)d_in[11];
    const float* Wo_e = (const float*)d_in[12];
    const float* W1   = (const float*)d_in[13];
    const float* b1   = (const float*)d_in[14];
    const float* W2   = (const float*)d_in[15];
    const float* b2   = (const float*)d_in[16];
    const float* ln1g = (const float*)d_in[17];
    const float* ln1b = (const float*)d_in[18];
    const float* ln2g = (const float*)d_in[19];
    const float* ln2b = (const float*)d_in[20];
    const float* ln3g = (const float*)d_in[21];
    const float* ln3b = (const float*)d_in[22];
    const float* Wrbf = (const float*)d_in[23];
    const float* Wc   = (const float*)d_in[24];
    const float* bc   = (const float*)d_in[25];

    float* buf = nullptr;
    cudaGetSymbolAddress((void**)&buf, g_buf);
    float* h    = buf + OFF_H;
    float* qb   = buf + OFF_Q;
    float* kb   = qb + E_ * D_;
    float* vb   = qb + 2 * E_ * D_;
    float* att  = buf + OFF_ATT;
    float* mid  = buf + OFF_MID;
    float* rbf  = buf + OFF_RBF;
    float* px   = buf + OFF_PX;
    float* xb   = buf + OFF_X;
    int4*  meta = (int4*)(buf + OFF_META);
    float* rbfW = buf + OFF_RBFW;   // rbfW for layers 1,2 (layer 0 folds into h)

    dim3 g1(1, E_ / 32, 1);          // 96 blocks
    dim3 g3(1, E_ / 32, 3);          // 288 blocks
    dim3 gF(FF_ / 128, E_ / 32, 1);  // 384 blocks
    dim3 gAttn(E_ / 8, H_);          // 384 blocks

    prep_kernel<<<(E_ + 127) / 128, 128>>>(edge_index, block_ids, node_coords,
                                           edge_coords, meta, rbf, px, xb);
    build_kernel<<<E_, 128>>>(meta);

    // rbfW_l = rbf @ Wrbf[l] for all 3 layers in one launch.
    // z=0 -> h = edge_features + rbfW_0 (layer-0 h'); z=1,2 -> rbfW buffers.
    gemm_kernel<5><<<g3, 256>>>(rbf, Wrbf, Wrbf + R_ * D_, Wrbf + 2 * R_ * D_,
                                h, rbfW, edge_features, E_, R_, D_,
                                nullptr, nullptr, nullptr, nullptr, nullptr,
                                nullptr, nullptr, nullptr);

    for (int l = 0; l < L_; l++) {
        const int DD = D_ * D_;
        const float* nextRbfW = (l < 2) ? (rbfW + (size_t)l * E_ * D_) : nullptr;

        // --- intra attention ---
        gemm_kernel<0><<<g3, 256>>>(h, Wq_a + l * DD, Wk_a + l * DD, Wv_a + l * DD,
                                    qb, nullptr, nullptr, E_, D_, D_,
                                    nullptr, nullptr, nullptr, nullptr, nullptr,
                                    nullptr, nullptr, nullptr);
        attn_kernel<true><<<gAttn, 256>>>(qb, kb, vb, xb, att, px);
        gemm_kernel<3><<<g1, 256>>>(att, Wo_a + l * DD, nullptr, nullptr,
                                    h, nullptr, h, E_, D_, D_,
                                    nullptr, ln1g + l * D_, ln1b + l * D_,
                                    nullptr, nullptr, nullptr, nullptr, nullptr);

        // --- inter attention ---
        gemm_kernel<0><<<g3, 256>>>(h, Wq_e + l * DD, Wk_e + l * DD, Wv_e + l * DD,
                                    qb, nullptr, nullptr, E_, D_, D_,
                                    nullptr, nullptr, nullptr, nullptr, nullptr,
                                    nullptr, nullptr, nullptr);
        attn_kernel<false><<<gAttn, 256>>>(qb, kb, vb, xb, att, nullptr);
        gemm_kernel<3><<<g1, 256>>>(att, Wo_e + l * DD, nullptr, nullptr,
                                    h, nullptr, h, E_, D_, D_,
                                    nullptr, ln2g + l * D_, ln2b + l * D_,
                                    nullptr, nullptr, nullptr, nullptr, nullptr);

        // --- FFN (down-proj fuses residual+bias+LN+gate+x-update + next-layer rbf add)
        gemm_kernel<2><<<gF, 256>>>(h, W1 + (size_t)l * D_ * FF_, nullptr, nullptr,
                                    mid, nullptr, nullptr, E_, D_, FF_,
                                    b1 + l * FF_, nullptr, nullptr,
                                    nullptr, nullptr, nullptr, nullptr, nullptr);
        gemm_kernel<4><<<g1, 256>>>(mid, W2 + (size_t)l * FF_ * D_, nullptr, nullptr,
                                    h, nullptr, h, E_, FF_, D_,
                                    b2 + l * D_, ln3g + l * D_, ln3b + l * D_,
                                    Wc + l * D_, bc + l, px, xb, nextRbfW);
    }

    out_kernel<<<(out_size + 255) / 256, 256>>>(h, xb, (float*)d_out, out_size);
}

// round 12
// speedup vs baseline: 3.3052x; 1.1562x over previous
#include <cuda_runtime.h>
#include <math.h>

#define E_   3072
#define D_   128
#define H_   8
#define HD_  16
#define R_   64
#define FF_  512
#define L_   3
#define CAP_ 128

// ---------------- scratch (no allocations allowed) ----------------
#define OFF_H    0
#define OFF_Q    393216          // q,k,v contiguous -> batched GEMM dst
#define OFF_ATT  1572864
#define OFF_MID  2359296
#define OFF_RBF  3932160
#define OFF_PX   4128768
#define OFF_X    4137984
#define OFF_META 4147200
#define OFF_RBFW 4159488
#define OFF_PART 4945920         // FF2 split-K partials: 2 x E x 128
#define TOTAL_F  5732352

__device__ __align__(16) float g_buf[TOTAL_F];
__device__ int g_ilist[E_ * CAP_];
__device__ int g_xlist[E_ * CAP_];
__device__ int g_icnt[E_];
__device__ int g_xcnt[E_];

// ---------------- packed f32x2 helpers (Blackwell FFMA2) ----------------
typedef unsigned long long ull;
__device__ __forceinline__ ull pack2(float lo, float hi) {
    ull r; asm("mov.b64 %0, {%1, %2};" : "=l"(r) : "f"(lo), "f"(hi)); return r;
}
__device__ __forceinline__ ull dup2(float v) {
    ull r; asm("mov.b64 %0, {%1, %1};" : "=l"(r) : "f"(v)); return r;
}
__device__ __forceinline__ ull fma2(ull a, ull b, ull c) {
    ull d; asm("fma.rn.f32x2 %0, %1, %2, %3;" : "=l"(d) : "l"(a), "l"(b), "l"(c)); return d;
}
__device__ __forceinline__ float2 unpk(ull v) {
    float lo, hi; asm("mov.b64 {%0, %1}, %2;" : "=f"(lo), "=f"(hi) : "l"(v));
    return make_float2(lo, hi);
}

// ---------------- prep: edge meta + rbf + zero px + copy x ----------------
__global__ void prep_kernel(const int* __restrict__ ei, const int* __restrict__ bid,
                            const float* __restrict__ nc, const float* __restrict__ ec,
                            int4* __restrict__ meta, float* __restrict__ rbf,
                            float* __restrict__ px, float* __restrict__ xb) {
    int e = blockIdx.x * 128 + threadIdx.x;
    if (e >= E_) return;
    int s = ei[e], d = ei[E_ + e];
    meta[e] = make_int4(s, d, bid[s], bid[d]);
    px[e*3+0] = 0.f; px[e*3+1] = 0.f; px[e*3+2] = 0.f;
    xb[e*3+0] = ec[e*3+0]; xb[e*3+1] = ec[e*3+1]; xb[e*3+2] = ec[e*3+2];
    float dx = nc[d*3+0] - nc[s*3+0];
    float dy = nc[d*3+1] - nc[s*3+1];
    float dz = nc[d*3+2] - nc[s*3+2];
    float dist = sqrtf(dx*dx + dy*dy + dz*dz);
    float t = fminf(dist * 0.1f, 1.0f);
    float fc = 0.5f * (cosf(3.14159265358979323846f * t) + 1.0f);
    const float inw = 64.0f / 10.0f;   // 1/width, width = CUTOFF/R
    #pragma unroll 8
    for (int r = 0; r < R_; r++) {
        float c = 10.0f * (float)r / 63.0f;   // linspace(0,10,64)
        float u = (dist - c) * inw;
        rbf[e * R_ + r] = expf(-u * u) * fc;
    }
}

// ---------------- build neighbor lists (once; layer/head-invariant) ----------
__global__ void __launch_bounds__(128) build_kernel(const int4* __restrict__ meta) {
    __shared__ int ci, cx;
    int i = blockIdx.x, tid = threadIdx.x;
    if (tid == 0) { ci = 0; cx = 0; }
    __syncthreads();
    int4 mi = meta[i];
    for (int j = tid; j < E_; j += 128) {
        int4 mj = meta[j];
        bool ip = (mi.z == mj.z) && (mi.w == mj.w);
        bool share = (mi.x == mj.x) || (mi.x == mj.y) || (mi.y == mj.x) || (mi.y == mj.y);
        if (ip || (i == j)) {
            int p = atomicAdd(&ci, 1);
            if (p < CAP_) g_ilist[i * CAP_ + p] = j;
        }
        if ((share && !ip) || (i == j)) {
            int p = atomicAdd(&cx, 1);
            if (p < CAP_) g_xlist[i * CAP_ + p] = j;
        }
    }
    __syncthreads();
    if (tid == 0) {
        g_icnt[i] = min(ci, CAP_);
        g_xcnt[i] = min(cx, CAP_);
    }
}

// ====== fused GEMM, tile 32x128, BK=32, 256 threads, double-buffered, f32x2 =====
// A rows use leading dim lda; per-z A column offset azk (for split-K).
// EPI 0: C = A@B; z selects B0/B1/B2, C = C0 + z*M*128   (QKV / FF2 split-K parts)
// EPI 5: z selects B; C = A@B (+res if z==0); z=0 -> C0, z>0 -> C12+(z-1)*M*128
// EPI 2: C = silu(A@B + bias)                            (FFN up)
// EPI 3: C = LN(res + A@B)*g + b                         (attn o-proj)
template<int EPI>
__global__ void __launch_bounds__(256) gemm_kernel(
    const float* __restrict__ A, const float* __restrict__ B0,
    const float* __restrict__ B1, const float* __restrict__ B2,
    float* C0, float* C12, const float* res,
    int M, int K, int lda, int azk, int Ntot,
    const float* __restrict__ bias,
    const float* __restrict__ lng, const float* __restrict__ lnb)
{
    __shared__ __align__(16) float As[2][32 * 34];   // k-major, stride 34
    __shared__ __align__(16) float Bs[2][32][128];
    int z = blockIdx.z;
    const float* B = (z == 0) ? B0 : ((z == 1) ? B1 : B2);
    const float* Ab = A + (size_t)z * azk;
    float* C;
    if (EPI == 0)      C = C0 + (size_t)z * M * 128;
    else if (EPI == 5) C = (z == 0) ? C0 : (C12 + (size_t)(z - 1) * M * 128);
    else               C = C0;

    int tid = threadIdx.x, tx = tid & 31, ty = tid >> 5;
    int m0 = blockIdx.y << 5, cb = blockIdx.x << 7;
    int nt = K >> 5;
    int am = tid >> 3, ak = (tid & 7) << 2;          // A: 32 rows x 32 k, all threads
    int brb = tid >> 5, bc4 = (tid & 31) << 2;       // B: rows brb+8j, j=0..3

    // prologue: tile 0 -> smem[0]
    float4 pa = *(const float4*)&Ab[(size_t)(m0 + am) * lda + ak];
    float4 pb[4];
    #pragma unroll
    for (int j = 0; j < 4; j++)
        pb[j] = *(const float4*)&B[(size_t)(brb + 8 * j) * Ntot + cb + bc4];
    As[0][(ak + 0) * 34 + am] = pa.x;
    As[0][(ak + 1) * 34 + am] = pa.y;
    As[0][(ak + 2) * 34 + am] = pa.z;
    As[0][(ak + 3) * 34 + am] = pa.w;
    #pragma unroll
    for (int j = 0; j < 4; j++)
        *(float4*)&Bs[0][brb + 8 * j][bc4] = pb[j];
    __syncthreads();

    ull c2[2][4];
    #pragma unroll
    for (int p = 0; p < 2; p++)
        #pragma unroll
        for (int c = 0; c < 4; c++) c2[p][c] = 0ULL;

    for (int t = 0; t < nt; t++) {
        int cur = t & 1;
        if (t + 1 < nt) {               // register prefetch overlaps compute
            int k0 = (t + 1) << 5;
            pa = *(const float4*)&Ab[(size_t)(m0 + am) * lda + k0 + ak];
            #pragma unroll
            for (int j = 0; j < 4; j++)
                pb[j] = *(const float4*)&B[(size_t)(k0 + brb + 8 * j) * Ntot + cb + bc4];
        }
        const float* Ac = As[cur];
        #pragma unroll
        for (int k = 0; k < 32; k++) {
            float2 a01 = *(const float2*)&Ac[k * 34 + ty * 4];
            float2 a23 = *(const float2*)&Ac[k * 34 + ty * 4 + 2];
            float4 bv  = *(const float4*)&Bs[cur][k][tx << 2];
            ull A01 = pack2(a01.x, a01.y);
            ull A23 = pack2(a23.x, a23.y);
            ull D0 = dup2(bv.x), D1 = dup2(bv.y), D2 = dup2(bv.z), D3 = dup2(bv.w);
            c2[0][0] = fma2(A01, D0, c2[0][0]);  c2[1][0] = fma2(A23, D0, c2[1][0]);
            c2[0][1] = fma2(A01, D1, c2[0][1]);  c2[1][1] = fma2(A23, D1, c2[1][1]);
            c2[0][2] = fma2(A01, D2, c2[0][2]);  c2[1][2] = fma2(A23, D2, c2[1][2]);
            c2[0][3] = fma2(A01, D3, c2[0][3]);  c2[1][3] = fma2(A23, D3, c2[1][3]);
        }
        if (t + 1 < nt) {
            int nb = cur ^ 1;
            As[nb][(ak + 0) * 34 + am] = pa.x;
            As[nb][(ak + 1) * 34 + am] = pa.y;
            As[nb][(ak + 2) * 34 + am] = pa.z;
            As[nb][(ak + 3) * 34 + am] = pa.w;
            #pragma unroll
            for (int j = 0; j < 4; j++)
                *(float4*)&Bs[nb][brb + 8 * j][bc4] = pb[j];
        }
        __syncthreads();
    }

    float val[4][4];
    #pragma unroll
    for (int p = 0; p < 2; p++)
        #pragma unroll
        for (int c = 0; c < 4; c++) {
            float2 u = unpk(c2[p][c]);
            val[2*p + 0][c] = u.x;
            val[2*p + 1][c] = u.y;
        }
    int cg = cb + (tx << 2);
    int r0 = m0 + ty * 4;

    if (EPI == 0 || EPI == 5) {
        #pragma unroll
        for (int i = 0; i < 4; i++) {
            float4 o = make_float4(val[i][0], val[i][1], val[i][2], val[i][3]);
            if (EPI == 5 && z == 0) {
                float4 rv = *(const float4*)&res[(size_t)(r0 + i) * Ntot + cg];
                o.x += rv.x; o.y += rv.y; o.z += rv.z; o.w += rv.w;
            }
            *(float4*)&C[(size_t)(r0 + i) * Ntot + cg] = o;
        }
        return;
    }
    if (EPI == 2) {
        float4 bv = *(const float4*)&bias[cg];
        #pragma unroll
        for (int i = 0; i < 4; i++) {
            float v0 = val[i][0] + bv.x, v1 = val[i][1] + bv.y;
            float v2 = val[i][2] + bv.z, v3 = val[i][3] + bv.w;
            v0 = v0 / (1.0f + __expf(-v0));
            v1 = v1 / (1.0f + __expf(-v1));
            v2 = v2 / (1.0f + __expf(-v2));
            v3 = v3 / (1.0f + __expf(-v3));
            *(float4*)&C[(size_t)(r0 + i) * Ntot + cg] = make_float4(v0, v1, v2, v3);
        }
        return;
    }

    // EPI 3: residual, row LayerNorm (warp owns full rows)
    #pragma unroll
    for (int i = 0; i < 4; i++) {
        float4 rv = *(const float4*)&res[(size_t)(r0 + i) * 128 + cg];
        val[i][0] += rv.x;  val[i][1] += rv.y;
        val[i][2] += rv.z;  val[i][3] += rv.w;
    }
    float s[4], sq[4];
    #pragma unroll
    for (int i = 0; i < 4; i++) {
        s[i]  = val[i][0] + val[i][1] + val[i][2] + val[i][3];
        sq[i] = val[i][0]*val[i][0] + val[i][1]*val[i][1]
              + val[i][2]*val[i][2] + val[i][3]*val[i][3];
    }
    #pragma unroll
    for (int o = 16; o > 0; o >>= 1) {
        #pragma unroll
        for (int i = 0; i < 4; i++) {
            s[i]  += __shfl_xor_sync(0xffffffffu, s[i],  o);
            sq[i] += __shfl_xor_sync(0xffffffffu, sq[i], o);
        }
    }
    float4 g4 = *(const float4*)&lng[cg];
    float4 b4 = *(const float4*)&lnb[cg];
    #pragma unroll
    for (int i = 0; i < 4; i++) {
        float mean = s[i] * (1.0f / 128.0f);
        float var  = fmaxf(sq[i] * (1.0f / 128.0f) - mean * mean, 0.0f);
        float rstd = rsqrtf(var + 1e-5f);
        float h0 = (val[i][0] - mean) * rstd * g4.x + b4.x;
        float h1 = (val[i][1] - mean) * rstd * g4.y + b4.y;
        float h2 = (val[i][2] - mean) * rstd * g4.z + b4.z;
        float h3 = (val[i][3] - mean) * rstd * g4.w + b4.w;
        *(float4*)&C[(size_t)(r0 + i) * 128 + cg] = make_float4(h0, h1, h2, h3);
    }
}

// ---- FF2 epilogue: t = LN(h + part0 + part1 + b2)*g + b; gate = tanh(t@Wc+bc);
//      x += gate*(x-px); px = 0; h = t (+ next layer's rbfW)
__global__ void __launch_bounds__(128) ff2_epi_kernel(
    const float* __restrict__ part, float* __restrict__ h,
    const float* __restrict__ b2,
    const float* __restrict__ g, const float* __restrict__ b,
    const float* __restrict__ Wc, const float* __restrict__ bc,
    float* __restrict__ px, float* __restrict__ x,
    const float* __restrict__ extra)
{
    int row = blockIdx.x, tid = threadIdx.x;
    int idx = row * 128 + tid;
    float t = h[idx] + part[idx] + part[E_ * 128 + idx] + b2[tid];
    float s = t, sq = t * t;
    #pragma unroll
    for (int o = 16; o > 0; o >>= 1) {
        s  += __shfl_xor_sync(0xffffffffu, s,  o);
        sq += __shfl_xor_sync(0xffffffffu, sq, o);
    }
    __shared__ float ss[4], sqs[4], gs[4];
    if ((tid & 31) == 0) { ss[tid >> 5] = s; sqs[tid >> 5] = sq; }
    __syncthreads();
    float S  = ss[0] + ss[1] + ss[2] + ss[3];
    float SQ = sqs[0] + sqs[1] + sqs[2] + sqs[3];
    float mean = S * (1.0f / 128.0f);
    float var = fmaxf(SQ * (1.0f / 128.0f) - mean * mean, 0.0f);
    float rstd = rsqrtf(var + 1e-5f);
    float hn = (t - mean) * rstd * g[tid] + b[tid];
    float gp = hn * Wc[tid];
    #pragma unroll
    for (int o = 16; o > 0; o >>= 1) gp += __shfl_xor_sync(0xffffffffu, gp, o);
    if ((tid & 31) == 0) gs[tid >> 5] = gp;
    __syncthreads();
    h[idx] = hn + (extra ? extra[idx] : 0.0f);
    if (tid < 3) {
        float gd = gs[0] + gs[1] + gs[2] + gs[3];
        float gt = tanhf(gd + bc[0]);
        float xv = x[row * 3 + tid];
        float pv = px[row * 3 + tid];
        x[row * 3 + tid]  = xv + gt * (xv - pv);
        px[row * 3 + tid] = 0.0f;   // ready for next layer / next replay
    }
}

// ---------------- sparse masked attention: one warp per (query, head) -----------
// Lanes split as (half, d): d = lane&15 is the head-dim, half = lane>>4 splits the
// neighbor list. Streaming softmax; halves merged via shfl at the end.
// In-loop shuffles use per-half masks (halves have different trip counts when n odd).
// INTRA also accumulates px[i] = mean_h sum_j p[h,i,j] * x[j] (atomicAdd, 3 lanes).
template<bool INTRA>
__global__ void __launch_bounds__(256) attn_kernel(
    const float* __restrict__ q, const float* __restrict__ k, const float* __restrict__ v,
    const float* __restrict__ x, float* __restrict__ out, float* __restrict__ px)
{
    int warp = threadIdx.x >> 5, lane = threadIdx.x & 31;
    int i = blockIdx.x * 8 + warp;
    int head = blockIdx.y;
    int off = head * HD_;
    int d = lane & 15, half = lane >> 4;
    unsigned hm = half ? 0xffff0000u : 0x0000ffffu;   // lanes of MY half only

    float qd = q[i * D_ + off + d];
    int n = INTRA ? g_icnt[i] : g_xcnt[i];
    const int* li = (INTRA ? g_ilist : g_xlist) + i * CAP_;

    float m = -1e30f, l = 0.0f, acc = 0.0f, ax = 0.0f;

    for (int t = half; t < n; t += 2) {
        int j = li[t];
        float s = qd * k[j * D_ + off + d];
        s += __shfl_xor_sync(hm, s, 8);
        s += __shfl_xor_sync(hm, s, 4);
        s += __shfl_xor_sync(hm, s, 2);
        s += __shfl_xor_sync(hm, s, 1);
        s *= 0.25f;  // 1/sqrt(16)
        float vd = v[j * D_ + off + d];
        float mn = fmaxf(m, s);
        float cc = __expf(m - mn), p = __expf(s - mn);
        l = l * cc + p;
        acc = acc * cc + p * vd;
        if (INTRA && d < 3) ax = ax * cc + p * x[j * 3 + d];
        m = mn;
    }

    // merge the two halves (all 32 lanes re-converged -> full mask legal)
    float m2 = __shfl_xor_sync(0xffffffffu, m, 16);
    float l2 = __shfl_xor_sync(0xffffffffu, l, 16);
    float a2 = __shfl_xor_sync(0xffffffffu, acc, 16);
    float mn = fmaxf(m, m2);
    float c1 = __expf(m - mn), c2 = __expf(m2 - mn);
    l = l * c1 + l2 * c2;
    acc = acc * c1 + a2 * c2;
    if (INTRA) {
        float x2 = __shfl_xor_sync(0xffffffffu, ax, 16);
        ax = ax * c1 + x2 * c2;
    }
    float inv = 1.0f / l;  // diag always present -> l > 0
    if (half == 0) {
        out[i * D_ + off + d] = acc * inv;
        if (INTRA && d < 3) atomicAdd(&px[i * 3 + d], ax * inv * 0.125f);
    }
}

// ---------------- output: concat(h, x) ----------------
__global__ void out_kernel(const float* __restrict__ h, const float* __restrict__ x,
                           float* __restrict__ out, int out_size)
{
    int i = blockIdx.x * 256 + threadIdx.x;
    if (i >= out_size) return;
    if (i < E_ * D_)               out[i] = h[i];
    else if (i < E_ * D_ + E_ * 3) out[i] = x[i - E_ * D_];
    else                           out[i] = 0.0f;
}

// ---------------- host ----------------
extern "C" void kernel_launch(void* const* d_in, const int* in_sizes, int n_in,
                              void* d_out, int out_size)
{
    const float* edge_features = (const float*)d_in[0];
    const float* edge_coords   = (const float*)d_in[1];
    const int*   edge_index    = (const int*)  d_in[2];
    const float* node_coords   = (const float*)d_in[3];
    const int*   block_ids     = (const int*)  d_in[4];
    const float* Wq_a = (const float*)d_in[5];
    const float* Wk_a = (const float*)d_in[6];
    const float* Wv_a = (const float*)d_in[7];
    const float* Wo_a = (const float*)d_in[8];
    const float* Wq_e = (const float*)d_in[9];
    const float* Wk_e = (const float*)d_in[10];
    const float* Wv_e = (const float*)d_in[11];
    const float* Wo_e = (const float*)d_in[12];
    const float* W1   = (const float*)d_in[13];
    const float* b1   = (const float*)d_in[14];
    const float* W2   = (const float*)d_in[15];
    const float* b2   = (const float*)d_in[16];
    const float* ln1g = (const float*)d_in[17];
    const float* ln1b = (const float*)d_in[18];
    const float* ln2g = (const float*)d_in[19];
    const float* ln2b = (const float*)d_in[20];
    const float* ln3g = (const float*)d_in[21];
    const float* ln3b = (const float*)d_in[22];
    const float* Wrbf = (const float*)d_in[23];
    const float* Wc   = (const float*)d_in[24];
    const float* bc   = (const float*)d_in[25];

    float* buf = nullptr;
    cudaGetSymbolAddress((void**)&buf, g_buf);
    float* h    = buf + OFF_H;
    float* qb   = buf + OFF_Q;
    float* kb   = qb + E_ * D_;
    float* vb   = qb + 2 * E_ * D_;
    float* att  = buf + OFF_ATT;
    float* mid  = buf + OFF_MID;
    float* rbf  = buf + OFF_RBF;
    float* px   = buf + OFF_PX;
    float* xb   = buf + OFF_X;
    int4*  meta = (int4*)(buf + OFF_META);
    float* rbfW = buf + OFF_RBFW;   // rbfW for layers 1,2 (layer 0 folds into h)
    float* part = buf + OFF_PART;   // FF2 split-K partials

    dim3 g1(1, E_ / 32, 1);          // 96 blocks
    dim3 g3(1, E_ / 32, 3);          // 288 blocks
    dim3 gF(FF_ / 128, E_ / 32, 1);  // 384 blocks
    dim3 g2(1, E_ / 32, 2);          // 192 blocks (FF2 split-K)
    dim3 gAttn(E_ / 8, H_);          // 384 blocks

    prep_kernel<<<(E_ + 127) / 128, 128>>>(edge_index, block_ids, node_coords,
                                           edge_coords, meta, rbf, px, xb);
    build_kernel<<<E_, 128>>>(meta);

    // rbfW_l = rbf @ Wrbf[l] for all 3 layers in one launch.
    // z=0 -> h = edge_features + rbfW_0 (layer-0 h'); z=1,2 -> rbfW buffers.
    gemm_kernel<5><<<g3, 256>>>(rbf, Wrbf, Wrbf + R_ * D_, Wrbf + 2 * R_ * D_,
                                h, rbfW, edge_features, E_, R_, R_, 0, D_,
                                nullptr, nullptr, nullptr);

    for (int l = 0; l < L_; l++) {
        const int DD = D_ * D_;
        const float* nextRbfW = (l < 2) ? (rbfW + (size_t)l * E_ * D_) : nullptr;

        // --- intra attention ---
        gemm_kernel<0><<<g3, 256>>>(h, Wq_a + l * DD, Wk_a + l * DD, Wv_a + l * DD,
                                    qb, nullptr, nullptr, E_, D_, D_, 0, D_,
                                    nullptr, nullptr, nullptr);
        attn_kernel<true><<<gAttn, 256>>>(qb, kb, vb, xb, att, px);
        gemm_kernel<3><<<g1, 256>>>(att, Wo_a + l * DD, nullptr, nullptr,
                                    h, nullptr, h, E_, D_, D_, 0, D_,
                                    nullptr, ln1g + l * D_, ln1b + l * D_);

        // --- inter attention ---
        gemm_kernel<0><<<g3, 256>>>(h, Wq_e + l * DD, Wk_e + l * DD, Wv_e + l * DD,
                                    qb, nullptr, nullptr, E_, D_, D_, 0, D_,
                                    nullptr, nullptr, nullptr);
        attn_kernel<false><<<gAttn, 256>>>(qb, kb, vb, xb, att, nullptr);
        gemm_kernel<3><<<g1, 256>>>(att, Wo_e + l * DD, nullptr, nullptr,
                                    h, nullptr, h, E_, D_, D_, 0, D_,
                                    nullptr, ln2g + l * D_, ln2b + l * D_);

        // --- FFN: up-proj (silu), then split-K down-proj + fused epilogue ---
        gemm_kernel<2><<<gF, 256>>>(h, W1 + (size_t)l * D_ * FF_, nullptr, nullptr,
                                    mid, nullptr, nullptr, E_, D_, D_, 0, FF_,
                                    b1 + l * FF_, nullptr, nullptr);
        // z in {0,1}: part_z = mid[:, z*256:(z+1)*256] @ W2[z*256:(z+1)*256, :]
        gemm_kernel<0><<<g2, 256>>>(mid, W2 + (size_t)l * FF_ * D_,
                                    W2 + (size_t)l * FF_ * D_ + 256 * D_, nullptr,
                                    part, nullptr, nullptr, E_, 256, FF_, 256, D_,
                                    nullptr, nullptr, nullptr);
        ff2_epi_kernel<<<E_, 128>>>(part, h, b2 + l * D_,
                                    ln3g + l * D_, ln3b + l * D_,
                                    Wc + l * D_, bc + l, px, xb, nextRbfW);
    }

    out_kernel<<<(out_size + 255) / 256, 256>>>(h, xb, (float*)d_out, out_size);
}